// round 1
// baseline (speedup 1.0000x reference)
#include <cuda_runtime.h>

// Problem constants (fixed shapes from reference setup_inputs)
#define NS   262144      // B*T*C samples
#define NEL  16777216    // B*T*C*F elements for reconstruction loss
#define KK   8           // mixture components
#define DD   8           // latent dim
#define NTRI 36          // D*(D+1)/2 upper-triangular entries
#define MPK  45          // per-k moment slots: gsum(1) + sz(8) + s2(36)

#define LAMBDA_ENERGY 0.1
#define LAMBDA_COV    0.005

// ---------------- device scratch (no allocations allowed) ----------------
__device__ double g_mom[KK * MPK];   // [k][0]=gsum, [1..8]=sum(g*z), [9..44]=sum(g*z_i*z_j) i<=j
__device__ double g_reconst;         // sum of squared diffs
__device__ double g_energy;          // sum of per-sample energies
__device__ double g_base;            // reconst_mean + lambda_cov * cov_diag
__device__ float  g_w2[KK * NTRI];   // exponent quadratic coeffs: diag -0.5*Cii, offdiag -Cij
__device__ float  g_bv[KK * DD];     // C * mu (linear term coeff, sign +)
__device__ float  g_cst[KK];         // -0.5*mu^T C mu + log(c_k)

// ---------------- helpers ----------------
__device__ __forceinline__ float warp_reduce(float v) {
#pragma unroll
    for (int o = 16; o > 0; o >>= 1) v += __shfl_xor_sync(0xFFFFFFFFu, v, o);
    return v;
}

__device__ __forceinline__ void block_reduce_atomic(float v, double* target) {
    __shared__ float red[32];
    v = warp_reduce(v);
    int lane = threadIdx.x & 31, wid = threadIdx.x >> 5;
    if (lane == 0) red[wid] = v;
    __syncthreads();
    if (wid == 0) {
        int nw = blockDim.x >> 5;
        v = (lane < nw) ? red[lane] : 0.0f;
        v = warp_reduce(v);
        if (lane == 0) atomicAdd(target, (double)v);
    }
}

// ---------------- pass 0: zero accumulators ----------------
__global__ void zero_kernel() {
    int t = threadIdx.x;
    if (t < KK * MPK) g_mom[t] = 0.0;
    if (t == 0) { g_reconst = 0.0; g_energy = 0.0; }
}

// ---------------- pass 1a: reconstruction loss sum ----------------
__global__ void reconst_kernel(const float4* __restrict__ x, const float4* __restrict__ xh) {
    const int n4 = NEL / 4;
    float acc = 0.0f;
    for (int i = blockIdx.x * blockDim.x + threadIdx.x; i < n4; i += gridDim.x * blockDim.x) {
        float4 a = x[i];
        float4 b = xh[i];
        float d0 = b.x - a.x, d1 = b.y - a.y, d2 = b.z - a.z, d3 = b.w - a.w;
        acc = fmaf(d0, d0, acc);
        acc = fmaf(d1, d1, acc);
        acc = fmaf(d2, d2, acc);
        acc = fmaf(d3, d3, acc);
    }
    block_reduce_atomic(acc, &g_reconst);
}

// ---------------- pass 1b: weighted GMM moments ----------------
// 8 threads per sample (one per k). lane%8 = k, groups of 8 lanes share a sample.
__global__ void moments_kernel(const float* __restrict__ z, const float* __restrict__ gamma) {
    const int k = threadIdx.x & 7;
    const int slot = (blockIdx.x * blockDim.x + threadIdx.x) >> 3;
    const int stride = (gridDim.x * blockDim.x) >> 3;

    float gs = 0.0f;
    float sz[DD];
    float s2[NTRI];
#pragma unroll
    for (int i = 0; i < DD; i++) sz[i] = 0.0f;
#pragma unroll
    for (int t = 0; t < NTRI; t++) s2[t] = 0.0f;

    for (int n = slot; n < NS; n += stride) {
        float4 z0 = *reinterpret_cast<const float4*>(z + (size_t)n * 8);
        float4 z1 = *reinterpret_cast<const float4*>(z + (size_t)n * 8 + 4);
        float zz[8] = {z0.x, z0.y, z0.z, z0.w, z1.x, z1.y, z1.z, z1.w};
        float g = __ldg(gamma + (size_t)n * 8 + k);
        gs += g;
        float gz[8];
#pragma unroll
        for (int i = 0; i < 8; i++) { gz[i] = g * zz[i]; sz[i] += gz[i]; }
        int t = 0;
#pragma unroll
        for (int i = 0; i < 8; i++)
#pragma unroll
            for (int j = i; j < 8; j++) { s2[t] = fmaf(gz[i], zz[j], s2[t]); t++; }
    }

    // combine the 4 lanes within this warp that share k (lane, lane^8, lane^16, lane^24)
    const unsigned m = 0xFFFFFFFFu;
    gs += __shfl_xor_sync(m, gs, 8);  gs += __shfl_xor_sync(m, gs, 16);
#pragma unroll
    for (int i = 0; i < DD; i++) {
        sz[i] += __shfl_xor_sync(m, sz[i], 8);
        sz[i] += __shfl_xor_sync(m, sz[i], 16);
    }
#pragma unroll
    for (int t = 0; t < NTRI; t++) {
        s2[t] += __shfl_xor_sync(m, s2[t], 8);
        s2[t] += __shfl_xor_sync(m, s2[t], 16);
    }

    __shared__ double sacc[KK * MPK];
    for (int i = threadIdx.x; i < KK * MPK; i += blockDim.x) sacc[i] = 0.0;
    __syncthreads();

    if ((threadIdx.x & 31) < 8) {
        double* p = sacc + k * MPK;
        atomicAdd(p, (double)gs);
#pragma unroll
        for (int i = 0; i < DD; i++) atomicAdd(p + 1 + i, (double)sz[i]);
#pragma unroll
        for (int t = 0; t < NTRI; t++) atomicAdd(p + 9 + t, (double)s2[t]);
    }
    __syncthreads();

    for (int i = threadIdx.x; i < KK * MPK; i += blockDim.x)
        atomicAdd(&g_mom[i], sacc[i]);
}

// ---------------- pass 2: per-component stats, 8x8 inverse+det, fold constants ----------------
__global__ void stats_kernel() {
    const int k = threadIdx.x;
    float cd = 0.0f;
    if (k < KK) {
        const double* mo = g_mom + k * MPK;
        double gs = mo[0];
        double mu[DD];
#pragma unroll
        for (int d = 0; d < DD; d++) mu[d] = mo[1 + d] / gs;

        float a[DD][DD], inv[DD][DD];
        {
            int t = 0;
#pragma unroll
            for (int i = 0; i < DD; i++)
#pragma unroll
                for (int j = i; j < DD; j++) {
                    double c = mo[9 + t] / gs - mu[i] * mu[j];
                    a[i][j] = (float)c;
                    a[j][i] = (float)c;
                    t++;
                }
        }
#pragma unroll
        for (int d = 0; d < DD; d++) a[d][d] += 1e-12f;  // EPS*I (matches ref)
#pragma unroll
        for (int d = 0; d < DD; d++) cd += 1.0f / a[d][d];

#pragma unroll
        for (int i = 0; i < DD; i++)
#pragma unroll
            for (int j = 0; j < DD; j++) inv[i][j] = (i == j) ? 1.0f : 0.0f;

        float det = 1.0f;
#pragma unroll
        for (int p = 0; p < DD; p++) {
            float piv = a[p][p];
            det *= piv;
            float r = 1.0f / piv;
#pragma unroll
            for (int c = 0; c < DD; c++) { a[p][c] *= r; inv[p][c] *= r; }
#pragma unroll
            for (int r2 = 0; r2 < DD; r2++) {
                if (r2 == p) continue;
                float f = a[r2][p];
#pragma unroll
                for (int c = 0; c < DD; c++) {
                    a[r2][c]   = fmaf(-f, a[p][c],   a[r2][c]);
                    inv[r2][c] = fmaf(-f, inv[p][c], inv[r2][c]);
                }
            }
        }

        // c_k = phi_k / sqrt(det_cov_k), det_cov_k = prod diag chol(2pi*cov) = (2pi)^4 sqrt(det)
        // => sqrt(det_cov_k) = (2pi)^2 * det^(1/4)
        float phi = (float)(gs / (double)NS);
        float ck = phi / (39.478417604357434f * sqrtf(sqrtf(det)));

        float muf[DD];
#pragma unroll
        for (int d = 0; d < DD; d++) muf[d] = (float)mu[d];

        {
            int t = 0;
#pragma unroll
            for (int i = 0; i < DD; i++)
#pragma unroll
                for (int j = i; j < DD; j++) {
                    g_w2[k * NTRI + t] = (i == j) ? (-0.5f * inv[i][i]) : (-inv[i][j]);
                    t++;
                }
        }
        float cst = 0.0f;
#pragma unroll
        for (int i = 0; i < DD; i++) {
            float b = 0.0f;
#pragma unroll
            for (int j = 0; j < DD; j++) b = fmaf(inv[i][j], muf[j], b);
            g_bv[k * DD + i] = b;
            cst = fmaf(b, muf[i], cst);
        }
        g_cst[k] = -0.5f * cst + logf(ck);
    }
    // reduce cov_diag over the 8 active lanes (lanes 8..31 hold 0)
    cd += __shfl_xor_sync(0xFFFFFFFFu, cd, 1);
    cd += __shfl_xor_sync(0xFFFFFFFFu, cd, 2);
    cd += __shfl_xor_sync(0xFFFFFFFFu, cd, 4);
    if (threadIdx.x == 0) {
        double rm = g_reconst / (double)NEL;
        g_base = rm + LAMBDA_COV * (double)cd;
    }
}

// ---------------- pass 3: per-sample energy ----------------
__global__ void energy_kernel(const float* __restrict__ z) {
    __shared__ __align__(16) float sw2[KK * NTRI];
    __shared__ __align__(16) float sbv[KK * DD];
    __shared__ float scst[KK];
    for (int i = threadIdx.x; i < KK * NTRI; i += blockDim.x) sw2[i] = g_w2[i];
    if (threadIdx.x < KK * DD) sbv[threadIdx.x] = g_bv[threadIdx.x];
    if (threadIdx.x < KK) scst[threadIdx.x] = g_cst[threadIdx.x];
    __syncthreads();

    float acc = 0.0f;
    for (int n = blockIdx.x * blockDim.x + threadIdx.x; n < NS; n += gridDim.x * blockDim.x) {
        float4 z0 = *reinterpret_cast<const float4*>(z + (size_t)n * 8);
        float4 z1 = *reinterpret_cast<const float4*>(z + (size_t)n * 8 + 4);
        float zz[8] = {z0.x, z0.y, z0.z, z0.w, z1.x, z1.y, z1.z, z1.w};

        // k-independent products z_i*z_j (i<=j)
        float p[NTRI];
        {
            int t = 0;
#pragma unroll
            for (int i = 0; i < 8; i++)
#pragma unroll
                for (int j = i; j < 8; j++) p[t++] = zz[i] * zz[j];
        }

        float s = 0.0f;
#pragma unroll
        for (int k = 0; k < KK; k++) {
            const float4* w4 = reinterpret_cast<const float4*>(sw2 + k * NTRI);
            float q = scst[k];
#pragma unroll
            for (int u = 0; u < 9; u++) {
                float4 w = w4[u];
                q = fmaf(w.x, p[4 * u + 0], q);
                q = fmaf(w.y, p[4 * u + 1], q);
                q = fmaf(w.z, p[4 * u + 2], q);
                q = fmaf(w.w, p[4 * u + 3], q);
            }
            const float4* b4 = reinterpret_cast<const float4*>(sbv + k * DD);
            float4 b0 = b4[0], b1 = b4[1];
            q = fmaf(b0.x, zz[0], q); q = fmaf(b0.y, zz[1], q);
            q = fmaf(b0.z, zz[2], q); q = fmaf(b0.w, zz[3], q);
            q = fmaf(b1.x, zz[4], q); q = fmaf(b1.y, zz[5], q);
            q = fmaf(b1.z, zz[6], q); q = fmaf(b1.w, zz[7], q);
            s += __expf(q);
        }
        acc += -__logf(s + 1e-12f);
    }
    block_reduce_atomic(acc, &g_energy);
}

// ---------------- pass 4: final scalar ----------------
__global__ void finalize_kernel(float* out) {
    out[0] = (float)(g_base + LAMBDA_ENERGY * (g_energy / (double)NS));
}

// ---------------- launch ----------------
extern "C" void kernel_launch(void* const* d_in, const int* in_sizes, int n_in,
                              void* d_out, int out_size) {
    const float* x     = (const float*)d_in[0];
    const float* xh    = (const float*)d_in[1];
    const float* z     = (const float*)d_in[2];
    const float* gamma = (const float*)d_in[3];
    float* out = (float*)d_out;

    zero_kernel<<<1, 512>>>();
    reconst_kernel<<<1184, 256>>>((const float4*)x, (const float4*)xh);
    moments_kernel<<<1184, 256>>>(z, gamma);
    stats_kernel<<<1, 32>>>();
    energy_kernel<<<592, 256>>>(z);
    finalize_kernel<<<1, 1>>>(out);
}

// round 2
// speedup vs baseline: 1.4792x; 1.4792x over previous
#include <cuda_runtime.h>

// Problem constants (fixed shapes from reference setup_inputs)
#define NS   262144      // B*T*C samples
#define NEL  16777216    // B*T*C*F elements for reconstruction loss
#define KK   8           // mixture components
#define DD   8           // latent dim
#define NTRI 36          // D*(D+1)/2 upper-triangular entries
#define MPK  45          // per-k moment slots: gsum(1) + sz(8) + s2(36)

#define LAMBDA_ENERGY 0.1
#define LAMBDA_COV    0.005

// ---------------- device scratch (no allocations allowed) ----------------
__device__ double g_mom[KK * MPK];   // [k][0]=gsum, [1..8]=sum(g*z), [9..44]=sum(g*z_i*z_j) i<=j
__device__ double g_reconst;         // sum of squared diffs
__device__ double g_energy;          // sum of per-sample energies
__device__ double g_base;            // reconst_mean + lambda_cov * cov_diag
__device__ float  g_w2[KK * NTRI];   // exponent quadratic coeffs: diag -0.5*Cii, offdiag -Cij
__device__ float  g_bv[KK * DD];     // C * mu (linear term coeff, sign +)
__device__ float  g_cst[KK];         // -0.5*mu^T C mu + log(c_k)

// upper-tri row start offsets for D=8: t(i,j) = TRI_ROW[i] + (j - i), j >= i
__device__ __constant__ int TRI_ROW[8] = {0, 8, 15, 21, 26, 30, 33, 35};

// ---------------- helpers ----------------
__device__ __forceinline__ float warp_reduce(float v) {
#pragma unroll
    for (int o = 16; o > 0; o >>= 1) v += __shfl_xor_sync(0xFFFFFFFFu, v, o);
    return v;
}

__device__ __forceinline__ void block_reduce_atomic(float v, double* target) {
    __shared__ float red[32];
    v = warp_reduce(v);
    int lane = threadIdx.x & 31, wid = threadIdx.x >> 5;
    if (lane == 0) red[wid] = v;
    __syncthreads();
    if (wid == 0) {
        int nw = blockDim.x >> 5;
        v = (lane < nw) ? red[lane] : 0.0f;
        v = warp_reduce(v);
        if (lane == 0) atomicAdd(target, (double)v);
    }
}

// ---------------- pass 0: zero accumulators ----------------
__global__ void zero_kernel() {
    int t = threadIdx.x;
    if (t < KK * MPK) g_mom[t] = 0.0;
    if (t == 0) { g_reconst = 0.0; g_energy = 0.0; }
}

// ---------------- pass 1a: reconstruction loss sum ----------------
__global__ void reconst_kernel(const float4* __restrict__ x, const float4* __restrict__ xh) {
    const int n4 = NEL / 4;
    float acc0 = 0.0f, acc1 = 0.0f;
    int i = blockIdx.x * blockDim.x + threadIdx.x;
    const int stride = gridDim.x * blockDim.x;
    for (; i + stride < n4; i += 2 * stride) {
        float4 a0 = x[i], b0 = xh[i];
        float4 a1 = x[i + stride], b1 = xh[i + stride];
        float d;
        d = b0.x - a0.x; acc0 = fmaf(d, d, acc0);
        d = b0.y - a0.y; acc0 = fmaf(d, d, acc0);
        d = b0.z - a0.z; acc0 = fmaf(d, d, acc0);
        d = b0.w - a0.w; acc0 = fmaf(d, d, acc0);
        d = b1.x - a1.x; acc1 = fmaf(d, d, acc1);
        d = b1.y - a1.y; acc1 = fmaf(d, d, acc1);
        d = b1.z - a1.z; acc1 = fmaf(d, d, acc1);
        d = b1.w - a1.w; acc1 = fmaf(d, d, acc1);
    }
    for (; i < n4; i += stride) {
        float4 a = x[i], b = xh[i];
        float d;
        d = b.x - a.x; acc0 = fmaf(d, d, acc0);
        d = b.y - a.y; acc0 = fmaf(d, d, acc0);
        d = b.z - a.z; acc0 = fmaf(d, d, acc0);
        d = b.w - a.w; acc0 = fmaf(d, d, acc0);
    }
    block_reduce_atomic(acc0 + acc1, &g_reconst);
}

// ---------------- pass 1b: weighted GMM moments ----------------
// 8 lanes per sample-slot (one per k). lane%8 = k, warp covers 4 slots.
// No shared atomics: per-warp partials -> shared stores -> tree sum -> one
// double atomicAdd per slot per block.
__global__ void moments_kernel(const float* __restrict__ z, const float* __restrict__ gamma) {
    const int lane = threadIdx.x & 31;
    const int k = lane & 7;
    const int warp = threadIdx.x >> 5;                 // 0..7
    const int slot = (blockIdx.x * blockDim.x + threadIdx.x) >> 3;
    const int stride = (gridDim.x * blockDim.x) >> 3;

    float gs = 0.0f;
    float sz[DD];
    float s2[NTRI];
#pragma unroll
    for (int i = 0; i < DD; i++) sz[i] = 0.0f;
#pragma unroll
    for (int t = 0; t < NTRI; t++) s2[t] = 0.0f;

    for (int n = slot; n < NS; n += stride) {
        float4 z0 = *reinterpret_cast<const float4*>(z + (size_t)n * 8);
        float4 z1 = *reinterpret_cast<const float4*>(z + (size_t)n * 8 + 4);
        float zz[8] = {z0.x, z0.y, z0.z, z0.w, z1.x, z1.y, z1.z, z1.w};
        float g = __ldg(gamma + (size_t)n * 8 + k);
        gs += g;
        float gz[8];
#pragma unroll
        for (int i = 0; i < 8; i++) { gz[i] = g * zz[i]; sz[i] += gz[i]; }
        int t = 0;
#pragma unroll
        for (int i = 0; i < 8; i++)
#pragma unroll
            for (int j = i; j < 8; j++) { s2[t] = fmaf(gz[i], zz[j], s2[t]); t++; }
    }

    // combine the 4 lanes within this warp that share k
    const unsigned m = 0xFFFFFFFFu;
    gs += __shfl_xor_sync(m, gs, 8);  gs += __shfl_xor_sync(m, gs, 16);
#pragma unroll
    for (int i = 0; i < DD; i++) {
        sz[i] += __shfl_xor_sync(m, sz[i], 8);
        sz[i] += __shfl_xor_sync(m, sz[i], 16);
    }
#pragma unroll
    for (int t = 0; t < NTRI; t++) {
        s2[t] += __shfl_xor_sync(m, s2[t], 8);
        s2[t] += __shfl_xor_sync(m, s2[t], 16);
    }

    __shared__ float sacc[8][KK * MPK];   // 8 warps x 360 floats = 11.5 KB
    if (lane < 8) {
        float* p = &sacc[warp][k * MPK];
        p[0] = gs;
#pragma unroll
        for (int i = 0; i < DD; i++) p[1 + i] = sz[i];
#pragma unroll
        for (int t = 0; t < NTRI; t++) p[9 + t] = s2[t];
    }
    __syncthreads();

    for (int i = threadIdx.x; i < KK * MPK; i += blockDim.x) {
        float v = 0.0f;
#pragma unroll
        for (int w = 0; w < 8; w++) v += sacc[w][i];
        atomicAdd(&g_mom[i], (double)v);
    }
}

// ---------------- pass 2: warp-parallel 8x8 inverse + det per component ----
// 8 warps, warp k handles component k. Lanes 0..7 own matrix rows; Gauss-
// Jordan via shuffle broadcasts. No spills (16 regs of matrix state/lane).
__global__ void __launch_bounds__(256) stats_kernel() {
    const int w = threadIdx.x >> 5;        // component k
    const int r = threadIdx.x & 31;        // lane; rows live in lanes 0..7
    const unsigned m = 0xFFFFFFFFu;
    __shared__ float s_cd[8];

    const double* mo = g_mom + w * MPK;
    const double gs = mo[0];

    // all lanes compute mu (needed for broadcast-free per-lane math)
    float mu[8];
    double mud[8];
#pragma unroll
    for (int j = 0; j < 8; j++) { mud[j] = mo[1 + j] / gs; mu[j] = (float)mud[j]; }

    float ar[8], ir[8];
    float cd = 0.0f;
    if (r < 8) {
#pragma unroll
        for (int j = 0; j < 8; j++) {
            int i0 = r < j ? r : j;
            int j0 = r < j ? j : r;
            int t = TRI_ROW[i0] + (j0 - i0);
            ar[j] = (float)(mo[9 + t] / gs - mud[r] * mud[j]);
            ir[j] = (r == j) ? 1.0f : 0.0f;
        }
        ar[r] += 1e-12f;                   // EPS*I, matches reference
        cd = 1.0f / ar[r];                 // cov_diag contribution
    } else {
#pragma unroll
        for (int j = 0; j < 8; j++) { ar[j] = (r == j + 24) ? 1.0f : 0.0f; ir[j] = 0.0f; }
    }

    float det = 1.0f;
#pragma unroll
    for (int p = 0; p < 8; p++) {
        float piv = __shfl_sync(m, ar[p], p);
        det *= piv;
        float rc = 1.0f / piv;
        float par[8], pir[8];
#pragma unroll
        for (int j = 0; j < 8; j++) par[j] = __shfl_sync(m, ar[j], p) * rc;
#pragma unroll
        for (int j = 0; j < 8; j++) pir[j] = __shfl_sync(m, ir[j], p) * rc;
        float f = ar[p];
        if (r == p) {
#pragma unroll
            for (int j = 0; j < 8; j++) { ar[j] = par[j]; ir[j] = pir[j]; }
        } else {
#pragma unroll
            for (int j = 0; j < 8; j++) {
                ar[j] = fmaf(-f, par[j], ar[j]);
                ir[j] = fmaf(-f, pir[j], ir[j]);
            }
        }
    }

    float cstp = 0.0f;
    if (r < 8) {
        // write quadratic coeffs for row r: entries t(r, j), j >= r
#pragma unroll
        for (int j = 0; j < 8; j++) {
            if (j >= r) {
                int t = TRI_ROW[r] + (j - r);
                g_w2[w * NTRI + t] = (j == r) ? (-0.5f * ir[r]) : (-ir[j]);
            }
        }
        float b = 0.0f;
#pragma unroll
        for (int j = 0; j < 8; j++) b = fmaf(ir[j], mu[j], b);
        g_bv[w * DD + r] = b;
        cstp = b * mu[r];
    }
    // reduce cst, cd over lanes 0..7 (lanes 8..31 hold 0)
#pragma unroll
    for (int o = 4; o > 0; o >>= 1) {
        cstp += __shfl_xor_sync(m, cstp, o);
        cd   += __shfl_xor_sync(m, cd, o);
    }
    if (r == 0) {
        // c_k = phi_k / ((2pi)^2 * det^(1/4));   (2pi)^2 = 39.4784176...
        float phi = (float)(gs / (double)NS);
        float ck = phi / (39.478417604357434f * sqrtf(sqrtf(det)));
        g_cst[w] = -0.5f * cstp + logf(ck);
        s_cd[w] = cd;
    }
    __syncthreads();
    if (threadIdx.x == 0) {
        float cdt = 0.0f;
#pragma unroll
        for (int i = 0; i < 8; i++) cdt += s_cd[i];
        g_base = g_reconst / (double)NEL + LAMBDA_COV * (double)cdt;
    }
}

// ---------------- pass 3: per-sample energy ----------------
__global__ void energy_kernel(const float* __restrict__ z) {
    __shared__ __align__(16) float sw2[KK * NTRI];
    __shared__ __align__(16) float sbv[KK * DD];
    __shared__ float scst[KK];
    for (int i = threadIdx.x; i < KK * NTRI; i += blockDim.x) sw2[i] = g_w2[i];
    if (threadIdx.x < KK * DD) sbv[threadIdx.x] = g_bv[threadIdx.x];
    if (threadIdx.x < KK) scst[threadIdx.x] = g_cst[threadIdx.x];
    __syncthreads();

    float acc = 0.0f;
    for (int n = blockIdx.x * blockDim.x + threadIdx.x; n < NS; n += gridDim.x * blockDim.x) {
        float4 z0 = *reinterpret_cast<const float4*>(z + (size_t)n * 8);
        float4 z1 = *reinterpret_cast<const float4*>(z + (size_t)n * 8 + 4);
        float zz[8] = {z0.x, z0.y, z0.z, z0.w, z1.x, z1.y, z1.z, z1.w};

        // k-independent products z_i*z_j (i<=j)
        float p[NTRI];
        {
            int t = 0;
#pragma unroll
            for (int i = 0; i < 8; i++)
#pragma unroll
                for (int j = i; j < 8; j++) p[t++] = zz[i] * zz[j];
        }

        float s = 0.0f;
#pragma unroll
        for (int k = 0; k < KK; k++) {
            const float4* w4 = reinterpret_cast<const float4*>(sw2 + k * NTRI);
            float q = scst[k];
#pragma unroll
            for (int u = 0; u < 9; u++) {
                float4 w = w4[u];
                q = fmaf(w.x, p[4 * u + 0], q);
                q = fmaf(w.y, p[4 * u + 1], q);
                q = fmaf(w.z, p[4 * u + 2], q);
                q = fmaf(w.w, p[4 * u + 3], q);
            }
            const float4* b4 = reinterpret_cast<const float4*>(sbv + k * DD);
            float4 b0 = b4[0], b1 = b4[1];
            q = fmaf(b0.x, zz[0], q); q = fmaf(b0.y, zz[1], q);
            q = fmaf(b0.z, zz[2], q); q = fmaf(b0.w, zz[3], q);
            q = fmaf(b1.x, zz[4], q); q = fmaf(b1.y, zz[5], q);
            q = fmaf(b1.z, zz[6], q); q = fmaf(b1.w, zz[7], q);
            s += __expf(q);
        }
        acc += -__logf(s + 1e-12f);
    }
    block_reduce_atomic(acc, &g_energy);
}

// ---------------- pass 4: final scalar ----------------
__global__ void finalize_kernel(float* out) {
    out[0] = (float)(g_base + LAMBDA_ENERGY * (g_energy / (double)NS));
}

// ---------------- launch ----------------
extern "C" void kernel_launch(void* const* d_in, const int* in_sizes, int n_in,
                              void* d_out, int out_size) {
    const float* x     = (const float*)d_in[0];
    const float* xh    = (const float*)d_in[1];
    const float* z     = (const float*)d_in[2];
    const float* gamma = (const float*)d_in[3];
    float* out = (float*)d_out;

    zero_kernel<<<1, 512>>>();
    reconst_kernel<<<592, 512>>>((const float4*)x, (const float4*)xh);
    moments_kernel<<<592, 256>>>(z, gamma);
    stats_kernel<<<1, 256>>>();
    energy_kernel<<<592, 256>>>(z);
    finalize_kernel<<<1, 1>>>(out);
}

// round 3
// speedup vs baseline: 1.7414x; 1.1773x over previous
#include <cuda_runtime.h>

// Problem constants (fixed shapes from reference setup_inputs)
#define NS   262144      // B*T*C samples
#define NEL  16777216    // B*T*C*F elements for reconstruction loss
#define KK   8           // mixture components
#define DD   8           // latent dim
#define NTRI 36          // D*(D+1)/2 upper-triangular entries
#define MPK  45          // per-k moment slots: gsum(1) + sz(8) + s2(36)

#define LAMBDA_ENERGY 0.1
#define LAMBDA_COV    0.005

#define RECONST_BLOCKS 592
#define MOMENT_BLOCKS  296
#define ENERGY_BLOCKS  296

// ---------------- device scratch (no allocations allowed) ----------------
__device__ double g_mom[KK * MPK];   // [k][0]=gsum, [1..8]=sum(g*z), [9..44]=sum(g*zi*zj) i<=j
__device__ double g_reconst;         // sum of squared diffs
__device__ double g_energy;          // sum of per-sample energies
__device__ double g_base;            // reconst_mean + lambda_cov * cov_diag
__device__ float  g_w2[KK * NTRI];   // exponent quadratic coeffs: diag -0.5*Cii, offdiag -Cij
__device__ float  g_bv[KK * DD];     // C * mu (linear term coeff)
__device__ float  g_cst[KK];         // -0.5*mu^T C mu + log(c_k)
__device__ unsigned g_ctr;           // energy last-block counter

// upper-tri row starts for D=8: t(i,j) = TRI_ROW[i] + (j - i), j >= i
__device__ __constant__ int TRI_ROW[8] = {0, 8, 15, 21, 26, 30, 33, 35};

// ---------------- helpers ----------------
__device__ __forceinline__ float warp_reduce(float v) {
#pragma unroll
    for (int o = 16; o > 0; o >>= 1) v += __shfl_xor_sync(0xFFFFFFFFu, v, o);
    return v;
}

__device__ __forceinline__ void block_reduce_atomic(float v, double* target) {
    __shared__ float red[32];
    v = warp_reduce(v);
    int lane = threadIdx.x & 31, wid = threadIdx.x >> 5;
    if (lane == 0) red[wid] = v;
    __syncthreads();
    if (wid == 0) {
        int nw = blockDim.x >> 5;
        v = (lane < nw) ? red[lane] : 0.0f;
        v = warp_reduce(v);
        if (lane == 0) atomicAdd(target, (double)v);
    }
}

// ---------------- pass 0: zero accumulators ----------------
__global__ void zero_kernel() {
    int t = threadIdx.x;
    if (t < KK * MPK) g_mom[t] = 0.0;
    if (t == 0) { g_reconst = 0.0; g_energy = 0.0; g_ctr = 0u; }
}

// ---------------- fused pass 1: reconst sum + GMM moments ----------------
__device__ void reconst_part(const float4* __restrict__ x, const float4* __restrict__ xh,
                             int bid) {
    const int n4 = NEL / 4;
    float acc0 = 0.0f, acc1 = 0.0f;
    int i = bid * blockDim.x + threadIdx.x;
    const int stride = RECONST_BLOCKS * blockDim.x;
    for (; i + stride < n4; i += 2 * stride) {
        float4 a0 = x[i], b0 = xh[i];
        float4 a1 = x[i + stride], b1 = xh[i + stride];
        float d;
        d = b0.x - a0.x; acc0 = fmaf(d, d, acc0);
        d = b0.y - a0.y; acc0 = fmaf(d, d, acc0);
        d = b0.z - a0.z; acc0 = fmaf(d, d, acc0);
        d = b0.w - a0.w; acc0 = fmaf(d, d, acc0);
        d = b1.x - a1.x; acc1 = fmaf(d, d, acc1);
        d = b1.y - a1.y; acc1 = fmaf(d, d, acc1);
        d = b1.z - a1.z; acc1 = fmaf(d, d, acc1);
        d = b1.w - a1.w; acc1 = fmaf(d, d, acc1);
    }
    for (; i < n4; i += stride) {
        float4 a = x[i], b = xh[i];
        float d;
        d = b.x - a.x; acc0 = fmaf(d, d, acc0);
        d = b.y - a.y; acc0 = fmaf(d, d, acc0);
        d = b.z - a.z; acc0 = fmaf(d, d, acc0);
        d = b.w - a.w; acc0 = fmaf(d, d, acc0);
    }
    block_reduce_atomic(acc0 + acc1, &g_reconst);
}

// 8 lanes per sample-slot (one per k). lane%8 = k, warp covers 4 slots.
__device__ void moments_part(const float* __restrict__ z, const float* __restrict__ gamma,
                             int bid) {
    const int lane = threadIdx.x & 31;
    const int k = lane & 7;
    const int warp = threadIdx.x >> 5;                 // 0..7
    const int slot = (bid * blockDim.x + threadIdx.x) >> 3;
    const int stride = (MOMENT_BLOCKS * blockDim.x) >> 3;

    float gs = 0.0f;
    float sz[DD];
    float s2[NTRI];
#pragma unroll
    for (int i = 0; i < DD; i++) sz[i] = 0.0f;
#pragma unroll
    for (int t = 0; t < NTRI; t++) s2[t] = 0.0f;

    for (int n = slot; n < NS; n += stride) {
        float4 z0 = *reinterpret_cast<const float4*>(z + (size_t)n * 8);
        float4 z1 = *reinterpret_cast<const float4*>(z + (size_t)n * 8 + 4);
        float zz[8] = {z0.x, z0.y, z0.z, z0.w, z1.x, z1.y, z1.z, z1.w};
        float g = __ldg(gamma + (size_t)n * 8 + k);
        gs += g;
        float gz[8];
#pragma unroll
        for (int i = 0; i < 8; i++) { gz[i] = g * zz[i]; sz[i] += gz[i]; }
        int t = 0;
#pragma unroll
        for (int i = 0; i < 8; i++)
#pragma unroll
            for (int j = i; j < 8; j++) { s2[t] = fmaf(gz[i], zz[j], s2[t]); t++; }
    }

    const unsigned m = 0xFFFFFFFFu;
    gs += __shfl_xor_sync(m, gs, 8);  gs += __shfl_xor_sync(m, gs, 16);
#pragma unroll
    for (int i = 0; i < DD; i++) {
        sz[i] += __shfl_xor_sync(m, sz[i], 8);
        sz[i] += __shfl_xor_sync(m, sz[i], 16);
    }
#pragma unroll
    for (int t = 0; t < NTRI; t++) {
        s2[t] += __shfl_xor_sync(m, s2[t], 8);
        s2[t] += __shfl_xor_sync(m, s2[t], 16);
    }

    __shared__ float sacc[8][KK * MPK];   // 8 warps x 360 floats = 11.5 KB
    if (lane < 8) {
        float* p = &sacc[warp][k * MPK];
        p[0] = gs;
#pragma unroll
        for (int i = 0; i < DD; i++) p[1 + i] = sz[i];
#pragma unroll
        for (int t = 0; t < NTRI; t++) p[9 + t] = s2[t];
    }
    __syncthreads();

    for (int i = threadIdx.x; i < KK * MPK; i += blockDim.x) {
        float v = 0.0f;
#pragma unroll
        for (int w = 0; w < 8; w++) v += sacc[w][i];
        atomicAdd(&g_mom[i], (double)v);
    }
}

__global__ void __launch_bounds__(256) fused_rm_kernel(
    const float4* __restrict__ x, const float4* __restrict__ xh,
    const float* __restrict__ z, const float* __restrict__ gamma) {
    if (blockIdx.x < RECONST_BLOCKS) {
        reconst_part(x, xh, blockIdx.x);
    } else {
        moments_part(z, gamma, blockIdx.x - RECONST_BLOCKS);
    }
}

// ---------------- pass 2: warp-parallel 8x8 inverse + det, all fp32 --------
// 8 warps, warp k = component k. Lanes 0..7 own matrix rows; Gauss-Jordan via
// shuffle broadcasts. No fp64 arithmetic except loads (fp64 divides were the
// 17us bottleneck last round).
__global__ void __launch_bounds__(256) stats_kernel() {
    const int w = threadIdx.x >> 5;        // component k
    const int r = threadIdx.x & 31;        // lane; rows live in lanes 0..7
    const unsigned m = 0xFFFFFFFFu;
    __shared__ float s_cd[8];

    const double* mo = g_mom + w * MPK;
    const float gsf = (float)mo[0];
    const float rgs = 1.0f / gsf;

    float mu[8];
#pragma unroll
    for (int j = 0; j < 8; j++) mu[j] = (float)mo[1 + j] * rgs;

    float ar[8], ir[8];
    float cd = 0.0f;
    if (r < 8) {
#pragma unroll
        for (int j = 0; j < 8; j++) {
            int i0 = r < j ? r : j;
            int j0 = r < j ? j : r;
            int t = TRI_ROW[i0] + (j0 - i0);
            ar[j] = fmaf(-mu[r], mu[j], (float)mo[9 + t] * rgs);
            ir[j] = (r == j) ? 1.0f : 0.0f;
        }
        ar[r] += 1e-12f;                   // EPS*I, matches reference
        cd = 1.0f / ar[r];                 // cov_diag contribution
    } else {
#pragma unroll
        for (int j = 0; j < 8; j++) { ar[j] = (r == j + 24) ? 1.0f : 0.0f; ir[j] = 0.0f; }
    }

    float det = 1.0f;
#pragma unroll
    for (int p = 0; p < 8; p++) {
        float piv = __shfl_sync(m, ar[p], p);
        det *= piv;
        float rc = 1.0f / piv;
        float par[8], pir[8];
#pragma unroll
        for (int j = 0; j < 8; j++) par[j] = __shfl_sync(m, ar[j], p) * rc;
#pragma unroll
        for (int j = 0; j < 8; j++) pir[j] = __shfl_sync(m, ir[j], p) * rc;
        float f = ar[p];
        if (r == p) {
#pragma unroll
            for (int j = 0; j < 8; j++) { ar[j] = par[j]; ir[j] = pir[j]; }
        } else {
#pragma unroll
            for (int j = 0; j < 8; j++) {
                ar[j] = fmaf(-f, par[j], ar[j]);
                ir[j] = fmaf(-f, pir[j], ir[j]);
            }
        }
    }

    float cstp = 0.0f;
    if (r < 8) {
#pragma unroll
        for (int j = 0; j < 8; j++) {
            if (j >= r) {
                int t = TRI_ROW[r] + (j - r);
                g_w2[w * NTRI + t] = (j == r) ? (-0.5f * ir[r]) : (-ir[j]);
            }
        }
        float b = 0.0f;
#pragma unroll
        for (int j = 0; j < 8; j++) b = fmaf(ir[j], mu[j], b);
        g_bv[w * DD + r] = b;
        cstp = b * mu[r];
    }
#pragma unroll
    for (int o = 4; o > 0; o >>= 1) {
        cstp += __shfl_xor_sync(m, cstp, o);
        cd   += __shfl_xor_sync(m, cd, o);
    }
    if (r == 0) {
        // c_k = phi_k / ((2pi)^2 * det^(1/4))
        float phi = gsf * (1.0f / (float)NS);
        float ck = phi / (39.478417604357434f * sqrtf(sqrtf(det)));
        g_cst[w] = -0.5f * cstp + logf(ck);
        s_cd[w] = cd;
    }
    __syncthreads();
    if (threadIdx.x == 0) {
        float cdt = 0.0f;
#pragma unroll
        for (int i = 0; i < 8; i++) cdt += s_cd[i];
        g_base = g_reconst / (double)NEL + LAMBDA_COV * (double)cdt;
    }
}

// ---------------- pass 3: per-sample energy + fused finalize ----------------
__global__ void __launch_bounds__(256) energy_kernel(const float* __restrict__ z,
                                                     float* __restrict__ out) {
    __shared__ __align__(16) float sw2[KK * NTRI];
    __shared__ __align__(16) float sbv[KK * DD];
    __shared__ float scst[KK];
    for (int i = threadIdx.x; i < KK * NTRI; i += blockDim.x) sw2[i] = g_w2[i];
    if (threadIdx.x < KK * DD) sbv[threadIdx.x] = g_bv[threadIdx.x];
    if (threadIdx.x < KK) scst[threadIdx.x] = g_cst[threadIdx.x];
    __syncthreads();

    float acc = 0.0f;
    for (int n = blockIdx.x * blockDim.x + threadIdx.x; n < NS; n += gridDim.x * blockDim.x) {
        float4 z0 = *reinterpret_cast<const float4*>(z + (size_t)n * 8);
        float4 z1 = *reinterpret_cast<const float4*>(z + (size_t)n * 8 + 4);
        float zz[8] = {z0.x, z0.y, z0.z, z0.w, z1.x, z1.y, z1.z, z1.w};

        float p[NTRI];
        {
            int t = 0;
#pragma unroll
            for (int i = 0; i < 8; i++)
#pragma unroll
                for (int j = i; j < 8; j++) p[t++] = zz[i] * zz[j];
        }

        float s = 0.0f;
#pragma unroll
        for (int k = 0; k < KK; k++) {
            const float4* w4 = reinterpret_cast<const float4*>(sw2 + k * NTRI);
            float q = scst[k];
#pragma unroll
            for (int u = 0; u < 9; u++) {
                float4 w = w4[u];
                q = fmaf(w.x, p[4 * u + 0], q);
                q = fmaf(w.y, p[4 * u + 1], q);
                q = fmaf(w.z, p[4 * u + 2], q);
                q = fmaf(w.w, p[4 * u + 3], q);
            }
            const float4* b4 = reinterpret_cast<const float4*>(sbv + k * DD);
            float4 b0 = b4[0], b1 = b4[1];
            q = fmaf(b0.x, zz[0], q); q = fmaf(b0.y, zz[1], q);
            q = fmaf(b0.z, zz[2], q); q = fmaf(b0.w, zz[3], q);
            q = fmaf(b1.x, zz[4], q); q = fmaf(b1.y, zz[5], q);
            q = fmaf(b1.z, zz[6], q); q = fmaf(b1.w, zz[7], q);
            s += __expf(q);
        }
        acc += -__logf(s + 1e-12f);
    }

    // block reduce, then last-block-finalize
    __shared__ float red[32];
    float v = warp_reduce(acc);
    int lane = threadIdx.x & 31, wid = threadIdx.x >> 5;
    if (lane == 0) red[wid] = v;
    __syncthreads();
    if (wid == 0) {
        int nw = blockDim.x >> 5;
        v = (lane < nw) ? red[lane] : 0.0f;
        v = warp_reduce(v);
        if (lane == 0) {
            atomicAdd(&g_energy, (double)v);
            __threadfence();
            unsigned prev = atomicAdd(&g_ctr, 1u);
            if (prev == (unsigned)(gridDim.x - 1)) {
                __threadfence();
                double e = *((volatile double*)&g_energy);
                out[0] = (float)(g_base + LAMBDA_ENERGY * (e / (double)NS));
            }
        }
    }
}

// ---------------- launch ----------------
extern "C" void kernel_launch(void* const* d_in, const int* in_sizes, int n_in,
                              void* d_out, int out_size) {
    const float* x     = (const float*)d_in[0];
    const float* xh    = (const float*)d_in[1];
    const float* z     = (const float*)d_in[2];
    const float* gamma = (const float*)d_in[3];
    float* out = (float*)d_out;

    zero_kernel<<<1, 512>>>();
    fused_rm_kernel<<<RECONST_BLOCKS + MOMENT_BLOCKS, 256>>>(
        (const float4*)x, (const float4*)xh, z, gamma);
    stats_kernel<<<1, 256>>>();
    energy_kernel<<<ENERGY_BLOCKS, 256>>>(z, out);
}

// round 4
// speedup vs baseline: 2.2395x; 1.2860x over previous
#include <cuda_runtime.h>

// Problem constants (fixed shapes from reference setup_inputs)
#define NS   262144      // B*T*C samples
#define NEL  16777216    // B*T*C*F elements for reconstruction loss
#define KK   8           // mixture components
#define DD   8           // latent dim
#define NTRI 36          // D*(D+1)/2 upper-triangular entries
#define MPK  45          // per-k moment slots: gsum(1) + sz(8) + s2(36)

#define LAMBDA_ENERGY 0.1
#define LAMBDA_COV    0.005

#define FUSED_BLOCKS   888   // 592 reconst (role 0,1) + 296 moments (role 2)
#define RECONST_BLOCKS 592
#define MOMENT_BLOCKS  296
#define ENERGY_BLOCKS  592

// ---------------- device scratch (zero-initialized at module load; the
// energy kernel's last block re-zeroes everything it dirtied, so each graph
// replay starts clean without a zeroing launch) ----------------
__device__ double g_mom[KK * MPK];   // [k][0]=gsum, [1..8]=sum(g*z), [9..44]=sum(g*zi*zj)
__device__ double g_reconst;         // sum of squared diffs
__device__ double g_energy;          // sum of per-sample energies
__device__ double g_base;            // reconst_mean + lambda_cov*cov_diag (overwritten each run)
__device__ float  g_w2[KK * NTRI];   // quad coeffs: diag -0.5*Cii, offdiag -Cij (overwritten)
__device__ float  g_bv[KK * DD];     // C*mu (overwritten)
__device__ float  g_cst[KK];         // -0.5*mu^T C mu + log(c_k) (overwritten)
__device__ unsigned g_ctr;           // energy last-block counter

// upper-tri row starts for D=8: t(i,j) = TRI_ROW[i] + (j - i), j >= i
__device__ __constant__ int TRI_ROW[8] = {0, 8, 15, 21, 26, 30, 33, 35};

// ---------------- helpers ----------------
__device__ __forceinline__ float warp_reduce(float v) {
#pragma unroll
    for (int o = 16; o > 0; o >>= 1) v += __shfl_xor_sync(0xFFFFFFFFu, v, o);
    return v;
}

__device__ __forceinline__ void block_reduce_atomic(float v, double* target) {
    __shared__ float red[32];
    v = warp_reduce(v);
    int lane = threadIdx.x & 31, wid = threadIdx.x >> 5;
    if (lane == 0) red[wid] = v;
    __syncthreads();
    if (wid == 0) {
        int nw = blockDim.x >> 5;
        v = (lane < nw) ? red[lane] : 0.0f;
        v = warp_reduce(v);
        if (lane == 0) atomicAdd(target, (double)v);
    }
}

// ---------------- fused pass 1: reconst sum + GMM moments ----------------
__device__ void reconst_part(const float4* __restrict__ x, const float4* __restrict__ xh,
                             int bid) {
    const int n4 = NEL / 4;
    float acc0 = 0.0f, acc1 = 0.0f;
    int i = bid * 256 + threadIdx.x;
    const int stride = RECONST_BLOCKS * 256;
    for (; i + stride < n4; i += 2 * stride) {
        float4 a0 = x[i], b0 = xh[i];
        float4 a1 = x[i + stride], b1 = xh[i + stride];
        float d;
        d = b0.x - a0.x; acc0 = fmaf(d, d, acc0);
        d = b0.y - a0.y; acc0 = fmaf(d, d, acc0);
        d = b0.z - a0.z; acc0 = fmaf(d, d, acc0);
        d = b0.w - a0.w; acc0 = fmaf(d, d, acc0);
        d = b1.x - a1.x; acc1 = fmaf(d, d, acc1);
        d = b1.y - a1.y; acc1 = fmaf(d, d, acc1);
        d = b1.z - a1.z; acc1 = fmaf(d, d, acc1);
        d = b1.w - a1.w; acc1 = fmaf(d, d, acc1);
    }
    for (; i < n4; i += stride) {
        float4 a = x[i], b = xh[i];
        float d;
        d = b.x - a.x; acc0 = fmaf(d, d, acc0);
        d = b.y - a.y; acc0 = fmaf(d, d, acc0);
        d = b.z - a.z; acc0 = fmaf(d, d, acc0);
        d = b.w - a.w; acc0 = fmaf(d, d, acc0);
    }
    block_reduce_atomic(acc0 + acc1, &g_reconst);
}

// 8 lanes per sample-slot (one per k). lane%8 = k, warp covers 4 slots.
__device__ void moments_part(const float* __restrict__ z, const float* __restrict__ gamma,
                             int bid) {
    const int lane = threadIdx.x & 31;
    const int k = lane & 7;
    const int warp = threadIdx.x >> 5;                 // 0..7
    const int slot = (bid * 256 + threadIdx.x) >> 3;
    const int stride = (MOMENT_BLOCKS * 256) >> 3;

    float gs = 0.0f;
    float sz[DD];
    float s2[NTRI];
#pragma unroll
    for (int i = 0; i < DD; i++) sz[i] = 0.0f;
#pragma unroll
    for (int t = 0; t < NTRI; t++) s2[t] = 0.0f;

    for (int n = slot; n < NS; n += stride) {
        float4 z0 = *reinterpret_cast<const float4*>(z + (size_t)n * 8);
        float4 z1 = *reinterpret_cast<const float4*>(z + (size_t)n * 8 + 4);
        float zz[8] = {z0.x, z0.y, z0.z, z0.w, z1.x, z1.y, z1.z, z1.w};
        float g = __ldg(gamma + (size_t)n * 8 + k);
        gs += g;
        float gz[8];
#pragma unroll
        for (int i = 0; i < 8; i++) { gz[i] = g * zz[i]; sz[i] += gz[i]; }
        int t = 0;
#pragma unroll
        for (int i = 0; i < 8; i++)
#pragma unroll
            for (int j = i; j < 8; j++) { s2[t] = fmaf(gz[i], zz[j], s2[t]); t++; }
    }

    const unsigned m = 0xFFFFFFFFu;
    gs += __shfl_xor_sync(m, gs, 8);  gs += __shfl_xor_sync(m, gs, 16);
#pragma unroll
    for (int i = 0; i < DD; i++) {
        sz[i] += __shfl_xor_sync(m, sz[i], 8);
        sz[i] += __shfl_xor_sync(m, sz[i], 16);
    }
#pragma unroll
    for (int t = 0; t < NTRI; t++) {
        s2[t] += __shfl_xor_sync(m, s2[t], 8);
        s2[t] += __shfl_xor_sync(m, s2[t], 16);
    }

    __shared__ float sacc[8][KK * MPK];   // 8 warps x 360 floats = 11.5 KB
    if (lane < 8) {
        float* p = &sacc[warp][k * MPK];
        p[0] = gs;
#pragma unroll
        for (int i = 0; i < DD; i++) p[1 + i] = sz[i];
#pragma unroll
        for (int t = 0; t < NTRI; t++) p[9 + t] = s2[t];
    }
    __syncthreads();

    for (int i = threadIdx.x; i < KK * MPK; i += 256) {
        float v = 0.0f;
#pragma unroll
        for (int w = 0; w < 8; w++) v += sacc[w][i];
        atomicAdd(&g_mom[i], (double)v);
    }
}

__global__ void __launch_bounds__(256) fused_rm_kernel(
    const float4* __restrict__ x, const float4* __restrict__ xh,
    const float* __restrict__ z, const float* __restrict__ gamma) {
    // interleave roles so both mix within scheduler waves
    int b = blockIdx.x;
    int role = b % 3;            // 0,1 -> reconst, 2 -> moments
    int grp = b / 3;
    if (role < 2) {
        reconst_part(x, xh, grp * 2 + role);
    } else {
        moments_part(z, gamma, grp);
    }
}

// ---------------- pass 2: warp-parallel 8x8 inverse + det, all fp32 --------
__global__ void __launch_bounds__(256) stats_kernel() {
    const int w = threadIdx.x >> 5;        // component k
    const int r = threadIdx.x & 31;        // lane; rows live in lanes 0..7
    const unsigned m = 0xFFFFFFFFu;
    __shared__ float s_cd[8];

    const double* mo = g_mom + w * MPK;
    const float gsf = (float)mo[0];
    const float rgs = 1.0f / gsf;

    float mu[8];
#pragma unroll
    for (int j = 0; j < 8; j++) mu[j] = (float)mo[1 + j] * rgs;

    float ar[8], ir[8];
    float cd = 0.0f;
    if (r < 8) {
#pragma unroll
        for (int j = 0; j < 8; j++) {
            int i0 = r < j ? r : j;
            int j0 = r < j ? j : r;
            int t = TRI_ROW[i0] + (j0 - i0);
            ar[j] = fmaf(-mu[r], mu[j], (float)mo[9 + t] * rgs);
            ir[j] = (r == j) ? 1.0f : 0.0f;
        }
        ar[r] += 1e-12f;                   // EPS*I, matches reference
        cd = 1.0f / ar[r];                 // cov_diag contribution
    } else {
#pragma unroll
        for (int j = 0; j < 8; j++) { ar[j] = (r == j + 24) ? 1.0f : 0.0f; ir[j] = 0.0f; }
    }

    float det = 1.0f;
#pragma unroll
    for (int p = 0; p < 8; p++) {
        float piv = __shfl_sync(m, ar[p], p);
        det *= piv;
        float rc = 1.0f / piv;
        float par[8], pir[8];
#pragma unroll
        for (int j = 0; j < 8; j++) par[j] = __shfl_sync(m, ar[j], p) * rc;
#pragma unroll
        for (int j = 0; j < 8; j++) pir[j] = __shfl_sync(m, ir[j], p) * rc;
        float f = ar[p];
        if (r == p) {
#pragma unroll
            for (int j = 0; j < 8; j++) { ar[j] = par[j]; ir[j] = pir[j]; }
        } else {
#pragma unroll
            for (int j = 0; j < 8; j++) {
                ar[j] = fmaf(-f, par[j], ar[j]);
                ir[j] = fmaf(-f, pir[j], ir[j]);
            }
        }
    }

    float cstp = 0.0f;
    if (r < 8) {
#pragma unroll
        for (int j = 0; j < 8; j++) {
            if (j >= r) {
                int t = TRI_ROW[r] + (j - r);
                g_w2[w * NTRI + t] = (j == r) ? (-0.5f * ir[r]) : (-ir[j]);
            }
        }
        float b = 0.0f;
#pragma unroll
        for (int j = 0; j < 8; j++) b = fmaf(ir[j], mu[j], b);
        g_bv[w * DD + r] = b;
        cstp = b * mu[r];
    }
#pragma unroll
    for (int o = 4; o > 0; o >>= 1) {
        cstp += __shfl_xor_sync(m, cstp, o);
        cd   += __shfl_xor_sync(m, cd, o);
    }
    if (r == 0) {
        // c_k = phi_k / ((2pi)^2 * det^(1/4))
        float phi = gsf * (1.0f / (float)NS);
        float ck = phi / (39.478417604357434f * sqrtf(sqrtf(det)));
        g_cst[w] = -0.5f * cstp + logf(ck);
        s_cd[w] = cd;
    }
    __syncthreads();
    if (threadIdx.x == 0) {
        float cdt = 0.0f;
#pragma unroll
        for (int i = 0; i < 8; i++) cdt += s_cd[i];
        g_base = g_reconst / (double)NEL + LAMBDA_COV * (double)cdt;
    }
}

// ---------------- pass 3: energy, lane-per-component, params in registers --
// Lane L handles component k = L&7; groups of 8 lanes share each sample
// (broadcast z loads). Coefficients live in registers (45/lane), loaded once.
// exp per lane, 3 xor-shuffles reduce over k, group leader accumulates -log.
// Last block finalizes the scalar AND re-zeroes all accumulators for the next
// graph replay.
__global__ void __launch_bounds__(256) energy_kernel(const float* __restrict__ z,
                                                     float* __restrict__ out) {
    const int lane = threadIdx.x & 31;
    const int k = lane & 7;

    // per-lane coefficient registers for component k
    float w[NTRI], bv[DD], cst;
#pragma unroll
    for (int t = 0; t < NTRI; t++) w[t] = g_w2[k * NTRI + t];
#pragma unroll
    for (int i = 0; i < DD; i++) bv[i] = g_bv[k * DD + i];
    cst = g_cst[k];

    const int slot = (blockIdx.x * blockDim.x + threadIdx.x) >> 3;
    const int stride = (gridDim.x * blockDim.x) >> 3;
    const unsigned m = 0xFFFFFFFFu;

    float acc = 0.0f;
    for (int n = slot; n < NS; n += stride) {
        float4 z0 = *reinterpret_cast<const float4*>(z + (size_t)n * 8);
        float4 z1 = *reinterpret_cast<const float4*>(z + (size_t)n * 8 + 4);
        float zz[8] = {z0.x, z0.y, z0.z, z0.w, z1.x, z1.y, z1.z, z1.w};

        float q = cst;
        int t = 0;
#pragma unroll
        for (int i = 0; i < 8; i++) {
            float row = bv[i];
#pragma unroll
            for (int j = i; j < 8; j++) { row = fmaf(w[t], zz[j], row); t++; }
            q = fmaf(zz[i], row, q);
        }
        float e = __expf(q);
        e += __shfl_xor_sync(m, e, 1);
        e += __shfl_xor_sync(m, e, 2);
        e += __shfl_xor_sync(m, e, 4);
        if (k == 0) acc += -__logf(e + 1e-12f);
    }

    // block reduce
    __shared__ float red[32];
    __shared__ bool is_last;
    float v = warp_reduce(acc);
    int wid = threadIdx.x >> 5;
    if (lane == 0) red[wid] = v;
    __syncthreads();
    if (threadIdx.x == 0) {
        float s = 0.0f;
        int nw = blockDim.x >> 5;
        for (int i = 0; i < nw; i++) s += red[i];
        atomicAdd(&g_energy, (double)s);
        __threadfence();
        unsigned prev = atomicAdd(&g_ctr, 1u);
        is_last = (prev == (unsigned)(gridDim.x - 1));
    }
    __syncthreads();
    if (is_last) {
        if (threadIdx.x == 0) {
            __threadfence();
            double e = *((volatile double*)&g_energy);
            out[0] = (float)(g_base + LAMBDA_ENERGY * (e / (double)NS));
            g_energy = 0.0;
            g_reconst = 0.0;
            g_ctr = 0u;
        }
        // re-zero moment accumulators for the next replay
        for (int i = threadIdx.x; i < KK * MPK; i += blockDim.x) g_mom[i] = 0.0;
    }
}

// ---------------- launch ----------------
extern "C" void kernel_launch(void* const* d_in, const int* in_sizes, int n_in,
                              void* d_out, int out_size) {
    const float* x     = (const float*)d_in[0];
    const float* xh    = (const float*)d_in[1];
    const float* z     = (const float*)d_in[2];
    const float* gamma = (const float*)d_in[3];
    float* out = (float*)d_out;

    fused_rm_kernel<<<FUSED_BLOCKS, 256>>>(
        (const float4*)x, (const float4*)xh, z, gamma);
    stats_kernel<<<1, 256>>>();
    energy_kernel<<<ENERGY_BLOCKS, 256>>>(z, out);
}